// round 11
// baseline (speedup 1.0000x reference)
#include <cuda_runtime.h>
#include <cuda_bf16.h>
#include <cstdint>

// ---------------------------------------------------------------------------
// RegionModel round-11: R10 with the conv1 ldmatrix alignment fix.
// mma.sync bf16 implicit GEMM, split-bf16 3-term fp32 emulation
// (Ah*Bh + Ah*Bl + Al*Bh). NHWC bf16 hi/lo activation planes. No im2col:
// each block stages the raw NHWC input tile (4 output rows + halo = 9 input
// rows) ONCE; ldmatrix reads A fragments directly with computed addresses.
// conv1: tile column t <-> ix = t-1, staged via 8B cp.async (zero-filled
// halo), so fragment addresses are 16B aligned. k = ty*16 + tx*4 + ci (KP=48),
// pad positions carry zero weights.
// ---------------------------------------------------------------------------

#define B_ 128
#define R_ 8

typedef unsigned int u32;
typedef unsigned long long u64;
typedef unsigned short u16;

// Activations (device globals)
__device__ __align__(16) __nv_bfloat16 g_imgh[(size_t)B_ * 256 * 256 * 4];
__device__ __align__(16) __nv_bfloat16 g_imgl[(size_t)B_ * 256 * 256 * 4];
__device__ __align__(16) __nv_bfloat16 g_b1h[(size_t)B_ * 128 * 128 * 32];
__device__ __align__(16) __nv_bfloat16 g_b1l[(size_t)B_ * 128 * 128 * 32];
__device__ __align__(16) __nv_bfloat16 g_b2h[(size_t)B_ * 64 * 64 * 64];
__device__ __align__(16) __nv_bfloat16 g_b2l[(size_t)B_ * 64 * 64 * 64];
__device__ float g_buf3[(size_t)B_ * 32 * 32 * 128];
__device__ float g_part[B_ * 8 * 128];
// Weight images: [R][NC][hi|lo][COUT][72 u16]
__device__ __align__(16) __nv_bfloat16 g_w1img[R_ * 1 * 2 * 32 * 72];
__device__ __align__(16) __nv_bfloat16 g_w2img[R_ * 5 * 2 * 64 * 72];
__device__ __align__(16) __nv_bfloat16 g_w3img[R_ * 9 * 2 * 128 * 72];

__device__ __forceinline__ u32 smem_u32(const void* p) {
    u32 a;
    asm("{ .reg .u64 t; cvta.to.shared.u64 t, %1; cvt.u32.u64 %0, t; }"
        : "=r"(a) : "l"(p));
    return a;
}
#define CP16(dst, src) \
    asm volatile("cp.async.cg.shared.global [%0], [%1], 16;" :: "r"(dst), "l"(src))
#define CP16Z(dst, src, sz) \
    asm volatile("cp.async.cg.shared.global [%0], [%1], 16, %2;" \
                 :: "r"(dst), "l"(src), "r"(sz))
#define CP8Z(dst, src, sz) \
    asm volatile("cp.async.ca.shared.global [%0], [%1], 8, %2;" \
                 :: "r"(dst), "l"(src), "r"(sz))
#define CP_COMMIT() asm volatile("cp.async.commit_group;" ::: "memory")
#define CP_WAIT0()  asm volatile("cp.async.wait_group 0;" ::: "memory")
#define CP_WAIT1()  asm volatile("cp.async.wait_group 1;" ::: "memory")
#define LDSM4(r, a) \
    asm volatile("ldmatrix.sync.aligned.m8n8.x4.shared.b16 {%0,%1,%2,%3}, [%4];" \
                 : "=r"((r)[0]), "=r"((r)[1]), "=r"((r)[2]), "=r"((r)[3]) : "r"(a))
#define MMA(acc, af, b0, b1) \
    asm volatile( \
        "mma.sync.aligned.m16n8k16.row.col.f32.bf16.bf16.f32 " \
        "{%0,%1,%2,%3}, {%4,%5,%6,%7}, {%8,%9}, {%0,%1,%2,%3};" \
        : "+f"((acc)[0]), "+f"((acc)[1]), "+f"((acc)[2]), "+f"((acc)[3]) \
        : "r"((af)[0]), "r"((af)[1]), "r"((af)[2]), "r"((af)[3]), "r"(b0), "r"(b1))

// ---------------------------------------------------------------------------
__global__ void __launch_bounds__(256) prep_img(const float* __restrict__ img,
                                                __nv_bfloat16* __restrict__ oh,
                                                __nv_bfloat16* __restrict__ ol)
{
    const int idx = blockIdx.x * 256 + threadIdx.x;
    if (idx >= B_ * 65536) return;
    const int b = idx >> 16, p = idx & 65535;
    const float* ip = img + (size_t)b * 3 * 65536 + p;
    u16 h[4], l[4];
#pragma unroll
    for (int c = 0; c < 3; c++) {
        const float x = __ldg(ip + (size_t)c * 65536);
        const __nv_bfloat16 hb = __float2bfloat16_rn(x);
        h[c] = __bfloat16_as_ushort(hb);
        l[c] = __bfloat16_as_ushort(__float2bfloat16_rn(x - __bfloat162float(hb)));
    }
    h[3] = 0; l[3] = 0;
    ((u64*)oh)[idx] = *(const u64*)h;
    ((u64*)ol)[idx] = *(const u64*)l;
}

// ---------------------------------------------------------------------------
// conv1 weights: k = ty*16 + tx*4 + ci (tx=3 / ci=3 pad -> 0). KP=48, NC=1.
// ---------------------------------------------------------------------------
__global__ void __launch_bounds__(256) prep_w1(const float* __restrict__ W,
                                               __nv_bfloat16* __restrict__ img)
{
    const int idx = blockIdx.x * 256 + threadIdx.x;
    if (idx >= R_ * 2 * 32 * 72) return;
    const int kl = idx % 72;
    int t = idx / 72;
    const int n  = t % 32; t /= 32;
    const int hl = t % 2;
    const int r  = t / 2;

    __nv_bfloat16 ob = __float2bfloat16_rn(0.0f);
    if (kl < 48) {
        const int ty = kl >> 4, rem = kl & 15, tx = rem >> 2, ci = rem & 3;
        if (tx < 3 && ci < 3) {
            const float w = W[(((size_t)r * 32 + n) * 3 + ci) * 9 + ty * 3 + tx];
            const __nv_bfloat16 h = __float2bfloat16_rn(w);
            ob = hl ? __float2bfloat16_rn(w - __bfloat162float(h)) : h;
        }
    }
    img[idx] = ob;
}

// conv2/3 weights: k = tap*CINP + ci
template <int CIN, int CINP, int COUT>
__global__ void __launch_bounds__(256) prep_w(const float* __restrict__ W,
                                              __nv_bfloat16* __restrict__ img)
{
    constexpr int KP = 9 * CINP;
    constexpr int NC = (KP + 63) / 64;
    const int idx = blockIdx.x * 256 + threadIdx.x;
    if (idx >= R_ * NC * 2 * COUT * 72) return;
    const int kl = idx % 72;
    int t = idx / 72;
    const int n  = t % COUT; t /= COUT;
    const int hl = t % 2;    t /= 2;
    const int c  = t % NC;
    const int r  = t / NC;

    __nv_bfloat16 ob = __float2bfloat16_rn(0.0f);
    const int k = c * 64 + kl;
    if (kl < 64 && k < KP) {
        const int tap = k / CINP, ci = k % CINP;
        if (tap < 9 && ci < CIN) {
            const float w = W[(((size_t)r * COUT + n) * CIN + ci) * 9 + tap];
            const __nv_bfloat16 h = __float2bfloat16_rn(w);
            ob = hl ? __float2bfloat16_rn(w - __bfloat162float(h)) : h;
        }
    }
    img[idx] = ob;
}

// ---------------------------------------------------------------------------
// Direct-from-tile implicit-GEMM conv.
// Block: 4 output rows (M = 4*HOUT). Input tile: 9 rows x ROWW px x CINP ch,
// hi+lo planes, staged ONCE. Weights: 2-slot ring over 64-k chunks.
// grid = (HOUT/4, 1, B). 256 threads, WM x WN warp grid.
// Tile column t <-> input ix = t - 1 (both FIRST and !FIRST).
// ---------------------------------------------------------------------------
template <int CINP, int LOGC, int COUT, int HOUT, int LOGH, int WM, int WN,
          bool FIRST, bool OUTF32>
__global__ void __launch_bounds__(256) conv_mma5(
    const __nv_bfloat16* __restrict__ src_h, const __nv_bfloat16* __restrict__ src_l,
    const __nv_bfloat16* __restrict__ wimg, const float* __restrict__ Bias,
    const int* __restrict__ region, float* __restrict__ outf,
    __nv_bfloat16* __restrict__ out_h, __nv_bfloat16* __restrict__ out_l)
{
    constexpr int HIN    = 2 * HOUT;
    constexpr int M      = 4 * HOUT;
    constexpr int KP     = FIRST ? 48 : 9 * CINP;
    constexpr int NC     = (KP + 63) / 64;
    constexpr int ROWW   = FIRST ? 260 : (2 * HOUT + 2);
    constexpr int APLANE = 9 * ROWW * CINP * 2;           // bytes per plane
    constexpr int BSSB   = 2 * COUT * 144;                // B ring slot bytes
    constexpr int MF     = M / (16 * WM);
    constexpr int NF     = COUT / (8 * WN);

    extern __shared__ __align__(16) char sm[];
    const u32 Au = smem_u32(sm);
    const u32 Bu = Au + 2 * APLANE;

    const int tid = threadIdx.x, lane = tid & 31, wid = tid >> 5;
    const int b   = blockIdx.z;
    const int r   = region[b] & (R_ - 1);
    const int oy0 = blockIdx.x * 4;
    const int iy0 = 8 * blockIdx.x - 1;
    const int g   = lane >> 2, tc = lane & 3;
    const int wm  = wid & (WM - 1), wn = wid / WM;
    const int M0  = wm * (M / WM);
    const int N0  = wn * (COUT / WN);
    const int khalf = lane >> 4;
    const int mrow16 = (lane & 7) + ((lane >> 3) & 1) * 8;

    // per-lane A row/col bases per mf
    int rowb[MF], jb[MF];
#pragma unroll
    for (int mf = 0; mf < MF; mf++) {
        const int m = M0 + mf * 16 + mrow16;
        rowb[mf] = 2 * (m >> LOGH);
        jb[mf]   = 2 * (m & (HOUT - 1));
    }
    const int bl_off = ((lane & 7) + ((lane >> 4) & 1) * 8) * 144
                     + ((lane >> 3) & 1) * 16;

    float acc[MF][NF][4];
#pragma unroll
    for (int mf = 0; mf < MF; mf++)
#pragma unroll
        for (int nf = 0; nf < NF; nf++)
            acc[mf][nf][0] = acc[mf][nf][1] = acc[mf][nf][2] = acc[mf][nf][3] = 0.f;

    const __nv_bfloat16* wr = wimg + (size_t)r * NC * 2 * COUT * 72;

    // ---- stage A tile once (both planes), then B chunk 0 ----
    if (FIRST) {
        // 8B per pixel; tile col t <-> ix = t-1 (16B-aligned fragment bases)
        constexpr int UA8 = 9 * 260;
        for (int i = tid; i < 2 * UA8; i += 256) {
            const int pl = (i >= UA8);
            const int u  = i - pl * UA8;
            const int rr = u / 260, t = u - rr * 260;
            const int iy = iy0 + rr;
            const int ix = t - 1;
            const bool v = ((unsigned)iy < (unsigned)HIN) &&
                           ((unsigned)ix < (unsigned)HIN);
            const size_t off = v ? (((size_t)(b * HIN + iy) * HIN + ix) * 4) : 0;
            const u32 d = Au + pl * APLANE + (rr * 260 + t) * 8;
            CP8Z(d, (pl ? src_l : src_h) + off, v ? 8 : 0);
        }
    } else {
        constexpr int UPR = ROWW * CINP / 8;   // 16B units per row
        constexpr int UA  = 9 * UPR;
        for (int i = tid; i < 2 * UA; i += 256) {
            const int pl = (i >= UA);
            const int u  = i - pl * UA;
            const int rr = u / UPR, uc = u - rr * UPR;
            const int iy = iy0 + rr;
            const int e0 = uc * 8;
            const int px = e0 >> LOGC;          // tile col, ix = px-1
            const bool v = ((unsigned)iy < (unsigned)HIN) && px >= 1 && px <= HIN;
            const size_t off = v
                ? (((size_t)(b * HIN + iy) * HIN + (px - 1)) * CINP
                   + (e0 & (CINP - 1))) : 0;
            const u32 d = Au + pl * APLANE + (rr * ROWW * CINP + e0) * 2;
            CP16Z(d, (pl ? src_l : src_h) + off, v ? 16 : 0);
        }
    }
    {
        const char* ws = (const char*)wr;
        for (int i = tid; i < 2 * COUT * 9; i += 256)
            CP16(Bu + i * 16, ws + (size_t)i * 16);
    }
    CP_COMMIT();

    for (int c = 0; c < NC; c++) {
        if (c + 1 < NC) {
            const char* ws = (const char*)(wr + (size_t)(c + 1) * 2 * COUT * 72);
            const u32 bs = Bu + ((c + 1) & 1) * BSSB;
            for (int i = tid; i < 2 * COUT * 9; i += 256)
                CP16(bs + i * 16, ws + (size_t)i * 16);
            CP_COMMIT();
            CP_WAIT1();
        } else {
            CP_WAIT0();
        }
        __syncthreads();

        const int rem = KP - c * 64;
        const int nks = (rem >= 64) ? 4 : ((rem + 15) >> 4);
        const u32 Bh = Bu + (c & 1) * BSSB;
        const u32 Bl = Bh + COUT * 144;

        for (int ks = 0; ks < nks; ks++) {
            const int kb = ks * 32;
            // per-lane A addresses for this k-step
            u32 aaddr[MF];
            if (FIRST) {
#pragma unroll
                for (int mf = 0; mf < MF; mf++)
                    aaddr[mf] = Au + (((rowb[mf] + ks) * ROWW
                                 + jb[mf] + khalf * 2) << 3);
            } else {
                const int k   = c * 64 + ks * 16 + khalf * 8;
                const int tap = k >> LOGC;
                const int ci0 = k & (CINP - 1);
                const int ty  = (tap * 11) >> 5;
                const int tx  = tap - ty * 3;
#pragma unroll
                for (int mf = 0; mf < MF; mf++)
                    aaddr[mf] = Au + ((((rowb[mf] + ty) * ROWW
                                 + jb[mf] + tx) << LOGC) + ci0) * 2;
            }
            // B fragments hi+lo
            u32 bfh[NF / 2][4], bfl[NF / 2][4];
#pragma unroll
            for (int np = 0; np < NF / 2; np++) {
                LDSM4(bfh[np], Bh + (N0 + np * 16) * 144 + kb + bl_off);
                LDSM4(bfl[np], Bl + (N0 + np * 16) * 144 + kb + bl_off);
            }
            // A hi, terms 0 (Ah*Bh) and 1 (Ah*Bl)
            u32 af[MF][4];
#pragma unroll
            for (int mf = 0; mf < MF; mf++) LDSM4(af[mf], aaddr[mf]);
#pragma unroll
            for (int mf = 0; mf < MF; mf++)
#pragma unroll
                for (int nf = 0; nf < NF; nf++) {
                    const u32 b0h = bfh[nf >> 1][(nf & 1) ? 2 : 0];
                    const u32 b1h = bfh[nf >> 1][(nf & 1) ? 3 : 1];
                    const u32 b0l = bfl[nf >> 1][(nf & 1) ? 2 : 0];
                    const u32 b1l = bfl[nf >> 1][(nf & 1) ? 3 : 1];
                    MMA(acc[mf][nf], af[mf], b0h, b1h);
                    MMA(acc[mf][nf], af[mf], b0l, b1l);
                }
            // A lo, term 2 (Al*Bh)
#pragma unroll
            for (int mf = 0; mf < MF; mf++) LDSM4(af[mf], aaddr[mf] + APLANE);
#pragma unroll
            for (int mf = 0; mf < MF; mf++)
#pragma unroll
                for (int nf = 0; nf < NF; nf++) {
                    const u32 b0h = bfh[nf >> 1][(nf & 1) ? 2 : 0];
                    const u32 b1h = bfh[nf >> 1][(nf & 1) ? 3 : 1];
                    MMA(acc[mf][nf], af[mf], b0h, b1h);
                }
        }
        __syncthreads();   // guard B slot reuse
    }

    // ---- epilogue: bias + ReLU ----
    const float* bias_g = Bias + r * COUT;
#pragma unroll
    for (int mf = 0; mf < MF; mf++)
#pragma unroll
        for (int half = 0; half < 2; half++) {
            const int m  = M0 + mf * 16 + g + half * 8;
            const int oy = oy0 + (m >> LOGH), ox = m & (HOUT - 1);
            const size_t base = (((size_t)b * HOUT + oy) * HOUT + ox) * COUT;
#pragma unroll
            for (int nf = 0; nf < NF; nf++) {
                const int n = N0 + nf * 8 + tc * 2;
                const float y0 = fmaxf(acc[mf][nf][half * 2 + 0] + __ldg(bias_g + n), 0.f);
                const float y1 = fmaxf(acc[mf][nf][half * 2 + 1] + __ldg(bias_g + n + 1), 0.f);
                if (OUTF32) {
                    *(float2*)(outf + base + n) = make_float2(y0, y1);
                } else {
                    const __nv_bfloat16 h0 = __float2bfloat16_rn(y0);
                    const __nv_bfloat16 h1 = __float2bfloat16_rn(y1);
                    const __nv_bfloat16 l0 = __float2bfloat16_rn(y0 - __bfloat162float(h0));
                    const __nv_bfloat16 l1 = __float2bfloat16_rn(y1 - __bfloat162float(h1));
                    *(u32*)(out_h + base + n) =
                        (u32)__bfloat16_as_ushort(h0) | ((u32)__bfloat16_as_ushort(h1) << 16);
                    *(u32*)(out_l + base + n) =
                        (u32)__bfloat16_as_ushort(l0) | ((u32)__bfloat16_as_ushort(l1) << 16);
                }
            }
        }
}

// ---------------------------------------------------------------------------
__global__ void __launch_bounds__(128) gap_part(const float* __restrict__ in,
                                                float* __restrict__ part)
{
    const int b = blockIdx.y, s = blockIdx.x, c = threadIdx.x;
    const float* p = in + ((size_t)b * 1024 + s * 128) * 128 + c;
    float a0 = 0, a1 = 0, a2 = 0, a3 = 0;
#pragma unroll 4
    for (int i = 0; i < 128; i += 4) {
        a0 += p[(size_t)(i + 0) * 128];
        a1 += p[(size_t)(i + 1) * 128];
        a2 += p[(size_t)(i + 2) * 128];
        a3 += p[(size_t)(i + 3) * 128];
    }
    part[(b * 8 + s) * 128 + c] = a0 + a1 + a2 + a3;
}

__global__ void __launch_bounds__(128) fc_k(const float* __restrict__ part,
                                            const float* __restrict__ fw,
                                            const float* __restrict__ fb,
                                            const int* __restrict__ region,
                                            float* __restrict__ out)
{
    __shared__ float f[128];
    const int b = blockIdx.x, tid = threadIdx.x;
    const int r = region[b] & (R_ - 1);
    float s = 0.0f;
#pragma unroll
    for (int q = 0; q < 8; q++) s += part[(b * 8 + q) * 128 + tid];
    f[tid] = s * (1.0f / 1024.0f);
    __syncthreads();
    if (tid < 32) {
        const float* w0 = fw + ((size_t)r * 2 + 0) * 128;
        const float* w1 = fw + ((size_t)r * 2 + 1) * 128;
        float p0 = 0.0f, p1 = 0.0f;
#pragma unroll
        for (int i = tid; i < 128; i += 32) {
            p0 = fmaf(f[i], w0[i], p0);
            p1 = fmaf(f[i], w1[i], p1);
        }
#pragma unroll
        for (int o = 16; o > 0; o >>= 1) {
            p0 += __shfl_down_sync(0xFFFFFFFFu, p0, o);
            p1 += __shfl_down_sync(0xFFFFFFFFu, p1, o);
        }
        if (tid == 0) {
            out[b * 2 + 0] = p0 + fb[r * 2 + 0];
            out[b * 2 + 1] = p1 + fb[r * 2 + 1];
        }
    }
}

// ---------------------------------------------------------------------------
extern "C" void kernel_launch(void* const* d_in, const int* in_sizes, int n_in,
                              void* d_out, int out_size)
{
    const float* image  = (const float*)d_in[0];
    const int*   region = (const int*)d_in[1];
    const float* w1     = (const float*)d_in[2];
    const float* b1     = (const float*)d_in[3];
    const float* w2     = (const float*)d_in[4];
    const float* b2     = (const float*)d_in[5];
    const float* w3     = (const float*)d_in[6];
    const float* b3     = (const float*)d_in[7];
    const float* fw     = (const float*)d_in[8];
    const float* fb     = (const float*)d_in[9];
    float* out = (float*)d_out;

    __nv_bfloat16 *imgh, *imgl, *b1h, *b1l, *b2h, *b2l, *w1img, *w2img, *w3img;
    float *buf3, *part;
    cudaGetSymbolAddress((void**)&imgh, g_imgh);
    cudaGetSymbolAddress((void**)&imgl, g_imgl);
    cudaGetSymbolAddress((void**)&b1h, g_b1h);
    cudaGetSymbolAddress((void**)&b1l, g_b1l);
    cudaGetSymbolAddress((void**)&b2h, g_b2h);
    cudaGetSymbolAddress((void**)&b2l, g_b2l);
    cudaGetSymbolAddress((void**)&buf3, g_buf3);
    cudaGetSymbolAddress((void**)&part, g_part);
    cudaGetSymbolAddress((void**)&w1img, g_w1img);
    cudaGetSymbolAddress((void**)&w2img, g_w2img);
    cudaGetSymbolAddress((void**)&w3img, g_w3img);

    prep_img<<<(B_ * 65536) / 256, 256>>>(image, imgh, imgl);
    prep_w1<<<(R_ * 2 * 32 * 72 + 255) / 256, 256>>>(w1, w1img);
    prep_w<32, 32, 64><<<(R_ * 5 * 2 * 64 * 72 + 255) / 256, 256>>>(w2, w2img);
    prep_w<64, 64, 128><<<(R_ * 9 * 2 * 128 * 72 + 255) / 256, 256>>>(w3, w3img);

    // smem: 2*APLANE + 2*BSSB
    const int SM1 = 2 * (9 * 260 * 4 * 2) + 2 * (2 * 32 * 144);     //  55872
    const int SM2 = 2 * (9 * 130 * 32 * 2) + 2 * (2 * 64 * 144);    // 186624
    const int SM3 = 2 * (9 * 66 * 64 * 2) + 2 * (2 * 128 * 144);    // 225792
    cudaFuncSetAttribute(conv_mma5<4, 2, 32, 128, 7, 8, 1, true, false>,
                         cudaFuncAttributeMaxDynamicSharedMemorySize, SM1);
    cudaFuncSetAttribute(conv_mma5<32, 5, 64, 64, 6, 4, 2, false, false>,
                         cudaFuncAttributeMaxDynamicSharedMemorySize, SM2);
    cudaFuncSetAttribute(conv_mma5<64, 6, 128, 32, 5, 2, 4, false, true>,
                         cudaFuncAttributeMaxDynamicSharedMemorySize, SM3);

    // conv1: M=512 (4 rows x 128), grid 32 x B
    conv_mma5<4, 2, 32, 128, 7, 8, 1, true, false><<<dim3(32, 1, B_), 256, SM1>>>(
        imgh, imgl, w1img, b1, region, nullptr, b1h, b1l);
    // conv2: M=256 (4 rows x 64), grid 16 x B
    conv_mma5<32, 5, 64, 64, 6, 4, 2, false, false><<<dim3(16, 1, B_), 256, SM2>>>(
        b1h, b1l, w2img, b2, region, nullptr, b2h, b2l);
    // conv3: M=128 (4 rows x 32), grid 8 x B -> fp32 NHWC
    conv_mma5<64, 6, 128, 32, 5, 2, 4, false, true><<<dim3(8, 1, B_), 256, SM3>>>(
        b2h, b2l, w3img, b3, region, buf3, nullptr, nullptr);

    gap_part<<<dim3(8, B_), 128>>>(buf3, part);
    fc_k<<<B_, 128>>>(part, fw, fb, region, out);
}

// round 12
// speedup vs baseline: 1.5509x; 1.5509x over previous
#include <cuda_runtime.h>
#include <cuda_bf16.h>
#include <cstdint>

// ---------------------------------------------------------------------------
// RegionModel round-12: R9 base (im2col-in-smem, 144B pitch = conflict-free
// ldmatrix) + occupancy fixes: conv3 split into 2 N-halves (64 ch/block),
// 2-slot cp.async pipeline with stage-distance 2 -> 110592 B smem ->
// 2 CTAs/SM for conv2+conv3. Split-bf16 3-term fp32 emulation
// (Ah*Bh + Ah*Bl + Al*Bh), NHWC bf16 hi/lo activation planes.
// ---------------------------------------------------------------------------

#define B_ 128
#define R_ 8

typedef unsigned int u32;
typedef unsigned long long u64;
typedef unsigned short u16;

// Activations (device globals)
__device__ __align__(16) __nv_bfloat16 g_imgh[(size_t)B_ * 256 * 256 * 4];
__device__ __align__(16) __nv_bfloat16 g_imgl[(size_t)B_ * 256 * 256 * 4];
__device__ __align__(16) __nv_bfloat16 g_b1h[(size_t)B_ * 128 * 128 * 32];
__device__ __align__(16) __nv_bfloat16 g_b1l[(size_t)B_ * 128 * 128 * 32];
__device__ __align__(16) __nv_bfloat16 g_b2h[(size_t)B_ * 64 * 64 * 64];
__device__ __align__(16) __nv_bfloat16 g_b2l[(size_t)B_ * 64 * 64 * 64];
__device__ float g_buf3[(size_t)B_ * 32 * 32 * 128];
__device__ float g_part[B_ * 8 * 128];
// Weight images: [R][NC][hi|lo][NTOT][72 u16], k = tap*CINP + ci, zero-padded
__device__ __align__(16) __nv_bfloat16 g_w1img[R_ * 1 * 2 * 32 * 72];
__device__ __align__(16) __nv_bfloat16 g_w2img[R_ * 5 * 2 * 64 * 72];
__device__ __align__(16) __nv_bfloat16 g_w3img[R_ * 9 * 2 * 128 * 72];

__device__ __forceinline__ u32 smem_u32(const void* p) {
    u32 a;
    asm("{ .reg .u64 t; cvta.to.shared.u64 t, %1; cvt.u32.u64 %0, t; }"
        : "=r"(a) : "l"(p));
    return a;
}
#define CP16(dst, src) \
    asm volatile("cp.async.cg.shared.global [%0], [%1], 16;" :: "r"(dst), "l"(src))
#define CP16Z(dst, src, sz) \
    asm volatile("cp.async.cg.shared.global [%0], [%1], 16, %2;" \
                 :: "r"(dst), "l"(src), "r"(sz))
#define CP8Z(dst, src, sz) \
    asm volatile("cp.async.ca.shared.global [%0], [%1], 8, %2;" \
                 :: "r"(dst), "l"(src), "r"(sz))
#define CP_COMMIT() asm volatile("cp.async.commit_group;" ::: "memory")
#define CP_WAIT0()  asm volatile("cp.async.wait_group 0;" ::: "memory")
#define CP_WAIT1()  asm volatile("cp.async.wait_group 1;" ::: "memory")
#define LDSM4(r, a) \
    asm volatile("ldmatrix.sync.aligned.m8n8.x4.shared.b16 {%0,%1,%2,%3}, [%4];" \
                 : "=r"((r)[0]), "=r"((r)[1]), "=r"((r)[2]), "=r"((r)[3]) : "r"(a))
#define MMA(acc, af, b0, b1) \
    asm volatile( \
        "mma.sync.aligned.m16n8k16.row.col.f32.bf16.bf16.f32 " \
        "{%0,%1,%2,%3}, {%4,%5,%6,%7}, {%8,%9}, {%0,%1,%2,%3};" \
        : "+f"((acc)[0]), "+f"((acc)[1]), "+f"((acc)[2]), "+f"((acc)[3]) \
        : "r"((af)[0]), "r"((af)[1]), "r"((af)[2]), "r"((af)[3]), "r"(b0), "r"(b1))

// ---------------------------------------------------------------------------
__global__ void __launch_bounds__(256) prep_img(const float* __restrict__ img,
                                                __nv_bfloat16* __restrict__ oh,
                                                __nv_bfloat16* __restrict__ ol)
{
    const int idx = blockIdx.x * 256 + threadIdx.x;
    if (idx >= B_ * 65536) return;
    const int b = idx >> 16, p = idx & 65535;
    const float* ip = img + (size_t)b * 3 * 65536 + p;
    u16 h[4], l[4];
#pragma unroll
    for (int c = 0; c < 3; c++) {
        const float x = __ldg(ip + (size_t)c * 65536);
        const __nv_bfloat16 hb = __float2bfloat16_rn(x);
        h[c] = __bfloat16_as_ushort(hb);
        l[c] = __bfloat16_as_ushort(__float2bfloat16_rn(x - __bfloat162float(hb)));
    }
    h[3] = 0; l[3] = 0;
    ((u64*)oh)[idx] = *(const u64*)h;
    ((u64*)ol)[idx] = *(const u64*)l;
}

// ---------------------------------------------------------------------------
template <int CIN, int CINP, int COUT>
__global__ void __launch_bounds__(256) prep_w(const float* __restrict__ W,
                                              __nv_bfloat16* __restrict__ img)
{
    constexpr int KP = 9 * CINP;
    constexpr int NC = (KP + 63) / 64;
    const int idx = blockIdx.x * 256 + threadIdx.x;
    if (idx >= R_ * NC * 2 * COUT * 72) return;
    const int kl = idx % 72;
    int t = idx / 72;
    const int n  = t % COUT; t /= COUT;
    const int hl = t % 2;    t /= 2;
    const int c  = t % NC;
    const int r  = t / NC;

    __nv_bfloat16 ob = __float2bfloat16_rn(0.0f);
    const int k = c * 64 + kl;
    if (kl < 64 && k < KP) {
        const int tap = k / CINP, ci = k % CINP;
        if (tap < 9 && ci < CIN) {
            const float w = W[(((size_t)r * COUT + n) * CIN + ci) * 9 + tap];
            const __nv_bfloat16 h = __float2bfloat16_rn(w);
            ob = hl ? __float2bfloat16_rn(w - __bfloat162float(h)) : h;
        }
    }
    img[idx] = ob;
}

// ---------------------------------------------------------------------------
// Implicit-GEMM conv. grid = (HOUT*HOUT/128, NTOT/COUT, B). 256 threads,
// WM x WN warp grid. Per slot: A hi|lo im2col [128x72 u16, 144B pitch] +
// B hi|lo [COUT x 72 u16]. 2-slot ring, stage-distance 2.
// ---------------------------------------------------------------------------
template <int CINP, int LOGC, int COUT, int NTOT, int HOUT, int LOGH,
          int WM, int WN, bool FIRST, bool OUTF32, int STAGES>
__global__ void __launch_bounds__(256) conv_mma6(
    const __nv_bfloat16* __restrict__ src_h, const __nv_bfloat16* __restrict__ src_l,
    const __nv_bfloat16* __restrict__ wimg, const float* __restrict__ Bias,
    const int* __restrict__ region, float* __restrict__ outf,
    __nv_bfloat16* __restrict__ out_h, __nv_bfloat16* __restrict__ out_l)
{
    constexpr int HIN  = 2 * HOUT;
    constexpr int KP   = 9 * CINP;
    constexpr int NC   = (KP + 63) / 64;
    constexpr int MF   = 128 / (16 * WM);
    constexpr int NF   = COUT / (8 * WN);
    constexpr int SSB  = 2 * 18432 + 2 * COUT * 144;   // slot bytes

    extern __shared__ __align__(16) char sm[];

    const int tid = threadIdx.x, lane = tid & 31, wid = tid >> 5;
    const int b   = blockIdx.z;
    const int px0 = blockIdx.x * 128;
    const int n0  = blockIdx.y * COUT;
    const int r   = region[b] & (R_ - 1);
    const int g   = lane >> 2, tc = lane & 3;
    const int wm  = wid & (WM - 1), wn = wid / WM;
    const int M0  = wm * (128 / WM);
    const int N0  = wn * (COUT / WN);

    const int al_off = ((lane & 7) + ((lane >> 3) & 1) * 8) * 144 + (lane >> 4) * 16;
    const int bl_off = ((lane & 7) + ((lane >> 4) & 1) * 8) * 144
                     + ((lane >> 3) & 1) * 16;

    float acc[MF][NF][4];
#pragma unroll
    for (int mf = 0; mf < MF; mf++)
#pragma unroll
        for (int nf = 0; nf < NF; nf++)
            acc[mf][nf][0] = acc[mf][nf][1] = acc[mf][nf][2] = acc[mf][nf][3] = 0.f;

    const __nv_bfloat16* wr = wimg + (size_t)r * NC * 2 * NTOT * 72;

    // ---- stage chunk c into slot s ----
    auto stage = [&](int c, int s) {
        char* sb = sm + s * SSB;
        const u32 au = smem_u32(sb);
        const u32 bu = au + 2 * 18432;
        // B: hi rows [n0, n0+COUT), then lo rows
        const u16* src = (const u16*)wr + (size_t)c * 2 * NTOT * 72;
        for (int i = tid; i < 2 * COUT * 9; i += 256) {
            const int half = i / (COUT * 9);
            const int rem  = i - half * COUT * 9;
            const int row  = rem / 9, u = rem - row * 9;
            const u16* sp = src + (size_t)half * NTOT * 72 + (n0 + row) * 72 + u * 8;
            CP16(bu + half * COUT * 144 + row * 144 + u * 16, sp);
        }
        // A: im2col k-slice (both planes)
        if (FIRST) {
            // CINP=4: k = tap*4 + ci; q = tap; zero rows q 9..11
            for (int i = tid; i < 2048; i += 256) {
                const int m = i >> 4, q = i & 15;
                if (q >= 12) continue;
                if (q < 9) {
                    const int px = px0 + m;
                    const int oy = px >> LOGH, ox = px & (HOUT - 1);
                    const int ty = q / 3, tx2 = q - 3 * ty;
                    const int iy = 2 * oy + ty - 1, ix = 2 * ox + tx2 - 1;
                    const bool v = (unsigned)iy < (unsigned)HIN &&
                                   (unsigned)ix < (unsigned)HIN;
                    const size_t off = v ? (((size_t)(b * HIN + iy) * HIN + ix) * 4) : 0;
                    const int sz = v ? 8 : 0;
                    const u32 d = au + m * 144 + q * 8;
                    CP8Z(d, src_h + off, sz);
                    CP8Z(d + 18432, src_l + off, sz);
                } else {
                    *(u64*)(sb + m * 144 + q * 8) = 0;
                    *(u64*)(sb + 18432 + m * 144 + q * 8) = 0;
                }
            }
        } else {
            for (int i = tid; i < 1024; i += 256) {
                const int m = i >> 3, q = i & 7;
                const int k = c * 64 + q * 8;
                if (k >= KP) continue;
                const int tap = k >> LOGC, ci0 = k & (CINP - 1);
                const int ty = tap / 3, tx2 = tap - 3 * ty;
                const int px = px0 + m;
                const int oy = px >> LOGH, ox = px & (HOUT - 1);
                const int iy = 2 * oy + ty - 1, ix = 2 * ox + tx2 - 1;
                const bool v = (unsigned)iy < (unsigned)HIN &&
                               (unsigned)ix < (unsigned)HIN;
                const size_t off = v
                    ? (((size_t)(b * HIN + iy) * HIN + ix) * CINP + ci0) : 0;
                const int sz = v ? 16 : 0;
                const u32 d = au + m * 144 + q * 16;
                CP16Z(d, src_h + off, sz);
                CP16Z(d + 18432, src_l + off, sz);
            }
        }
        CP_COMMIT();
    };

    // ---- MMA chunk c from slot s ----
    auto domma = [&](int c, int s) {
        const int rem = KP - c * 64;
        const int nks = (rem >= 64) ? 4 : ((rem + 15) >> 4);
        const u32 au  = smem_u32(sm + s * SSB);
        const u32 Ahi = au, Alo = au + 18432;
        const u32 Bhi = au + 2 * 18432, Blo = Bhi + COUT * 144;
#pragma unroll 4
        for (int ks = 0; ks < nks; ks++) {
            const int kb = ks * 32;
            u32 bfh[NF / 2][4], bfl[NF / 2][4];
#pragma unroll
            for (int np = 0; np < NF / 2; np++) {
                LDSM4(bfh[np], Bhi + (N0 + np * 16) * 144 + kb + bl_off);
                LDSM4(bfl[np], Blo + (N0 + np * 16) * 144 + kb + bl_off);
            }
            u32 af[MF][4];
#pragma unroll
            for (int mf = 0; mf < MF; mf++)
                LDSM4(af[mf], Ahi + (M0 + mf * 16) * 144 + kb + al_off);
#pragma unroll
            for (int mf = 0; mf < MF; mf++)
#pragma unroll
                for (int nf = 0; nf < NF; nf++) {
                    const u32 b0h = bfh[nf >> 1][(nf & 1) ? 2 : 0];
                    const u32 b1h = bfh[nf >> 1][(nf & 1) ? 3 : 1];
                    const u32 b0l = bfl[nf >> 1][(nf & 1) ? 2 : 0];
                    const u32 b1l = bfl[nf >> 1][(nf & 1) ? 3 : 1];
                    MMA(acc[mf][nf], af[mf], b0h, b1h);
                    MMA(acc[mf][nf], af[mf], b0l, b1l);
                }
#pragma unroll
            for (int mf = 0; mf < MF; mf++)
                LDSM4(af[mf], Alo + (M0 + mf * 16) * 144 + kb + al_off);
#pragma unroll
            for (int mf = 0; mf < MF; mf++)
#pragma unroll
                for (int nf = 0; nf < NF; nf++) {
                    const u32 b0h = bfh[nf >> 1][(nf & 1) ? 2 : 0];
                    const u32 b1h = bfh[nf >> 1][(nf & 1) ? 3 : 1];
                    MMA(acc[mf][nf], af[mf], b0h, b1h);
                }
        }
    };

    // ---- pipeline: 2 slots, stage-distance 2 ----
    stage(0, 0);
    if (STAGES > 1 && NC > 1) stage(1, 1);
    for (int c = 0; c < NC; c++) {
        if (STAGES > 1 && c + 1 < NC) { CP_WAIT1(); } else { CP_WAIT0(); }
        __syncthreads();
        domma(c, (STAGES > 1) ? (c & 1) : 0);
        if (STAGES > 1) {
            __syncthreads();
            if (c + 2 < NC) stage(c + 2, c & 1);
        }
    }

    // ---- epilogue: bias + ReLU ----
    const float* bias_g = Bias + r * NTOT + n0;
#pragma unroll
    for (int mf = 0; mf < MF; mf++)
#pragma unroll
        for (int half = 0; half < 2; half++) {
            const int m  = M0 + mf * 16 + g + half * 8;
            const int px = px0 + m;
            const int oy = px >> LOGH, ox = px & (HOUT - 1);
            const size_t base = (((size_t)b * HOUT + oy) * HOUT + ox) * NTOT + n0;
#pragma unroll
            for (int nf = 0; nf < NF; nf++) {
                const int n = N0 + nf * 8 + tc * 2;
                const float y0 = fmaxf(acc[mf][nf][half * 2 + 0] + __ldg(bias_g + n), 0.f);
                const float y1 = fmaxf(acc[mf][nf][half * 2 + 1] + __ldg(bias_g + n + 1), 0.f);
                if (OUTF32) {
                    *(float2*)(outf + base + n) = make_float2(y0, y1);
                } else {
                    const __nv_bfloat16 h0 = __float2bfloat16_rn(y0);
                    const __nv_bfloat16 h1 = __float2bfloat16_rn(y1);
                    const __nv_bfloat16 l0 = __float2bfloat16_rn(y0 - __bfloat162float(h0));
                    const __nv_bfloat16 l1 = __float2bfloat16_rn(y1 - __bfloat162float(h1));
                    *(u32*)(out_h + base + n) =
                        (u32)__bfloat16_as_ushort(h0) | ((u32)__bfloat16_as_ushort(h1) << 16);
                    *(u32*)(out_l + base + n) =
                        (u32)__bfloat16_as_ushort(l0) | ((u32)__bfloat16_as_ushort(l1) << 16);
                }
            }
        }
}

// ---------------------------------------------------------------------------
__global__ void __launch_bounds__(128) gap_part(const float* __restrict__ in,
                                                float* __restrict__ part)
{
    const int b = blockIdx.y, s = blockIdx.x, c = threadIdx.x;
    const float* p = in + ((size_t)b * 1024 + s * 128) * 128 + c;
    float a0 = 0, a1 = 0, a2 = 0, a3 = 0;
#pragma unroll 4
    for (int i = 0; i < 128; i += 4) {
        a0 += p[(size_t)(i + 0) * 128];
        a1 += p[(size_t)(i + 1) * 128];
        a2 += p[(size_t)(i + 2) * 128];
        a3 += p[(size_t)(i + 3) * 128];
    }
    part[(b * 8 + s) * 128 + c] = a0 + a1 + a2 + a3;
}

__global__ void __launch_bounds__(128) fc_k(const float* __restrict__ part,
                                            const float* __restrict__ fw,
                                            const float* __restrict__ fb,
                                            const int* __restrict__ region,
                                            float* __restrict__ out)
{
    __shared__ float f[128];
    const int b = blockIdx.x, tid = threadIdx.x;
    const int r = region[b] & (R_ - 1);
    float s = 0.0f;
#pragma unroll
    for (int q = 0; q < 8; q++) s += part[(b * 8 + q) * 128 + tid];
    f[tid] = s * (1.0f / 1024.0f);
    __syncthreads();
    if (tid < 32) {
        const float* w0 = fw + ((size_t)r * 2 + 0) * 128;
        const float* w1 = fw + ((size_t)r * 2 + 1) * 128;
        float p0 = 0.0f, p1 = 0.0f;
#pragma unroll
        for (int i = tid; i < 128; i += 32) {
            p0 = fmaf(f[i], w0[i], p0);
            p1 = fmaf(f[i], w1[i], p1);
        }
#pragma unroll
        for (int o = 16; o > 0; o >>= 1) {
            p0 += __shfl_down_sync(0xFFFFFFFFu, p0, o);
            p1 += __shfl_down_sync(0xFFFFFFFFu, p1, o);
        }
        if (tid == 0) {
            out[b * 2 + 0] = p0 + fb[r * 2 + 0];
            out[b * 2 + 1] = p1 + fb[r * 2 + 1];
        }
    }
}

// ---------------------------------------------------------------------------
extern "C" void kernel_launch(void* const* d_in, const int* in_sizes, int n_in,
                              void* d_out, int out_size)
{
    const float* image  = (const float*)d_in[0];
    const int*   region = (const int*)d_in[1];
    const float* w1     = (const float*)d_in[2];
    const float* b1     = (const float*)d_in[3];
    const float* w2     = (const float*)d_in[4];
    const float* b2     = (const float*)d_in[5];
    const float* w3     = (const float*)d_in[6];
    const float* b3     = (const float*)d_in[7];
    const float* fw     = (const float*)d_in[8];
    const float* fb     = (const float*)d_in[9];
    float* out = (float*)d_out;

    __nv_bfloat16 *imgh, *imgl, *b1h, *b1l, *b2h, *b2l, *w1img, *w2img, *w3img;
    float *buf3, *part;
    cudaGetSymbolAddress((void**)&imgh, g_imgh);
    cudaGetSymbolAddress((void**)&imgl, g_imgl);
    cudaGetSymbolAddress((void**)&b1h, g_b1h);
    cudaGetSymbolAddress((void**)&b1l, g_b1l);
    cudaGetSymbolAddress((void**)&b2h, g_b2h);
    cudaGetSymbolAddress((void**)&b2l, g_b2l);
    cudaGetSymbolAddress((void**)&buf3, g_buf3);
    cudaGetSymbolAddress((void**)&part, g_part);
    cudaGetSymbolAddress((void**)&w1img, g_w1img);
    cudaGetSymbolAddress((void**)&w2img, g_w2img);
    cudaGetSymbolAddress((void**)&w3img, g_w3img);

    prep_img<<<(B_ * 65536) / 256, 256>>>(image, imgh, imgl);
    prep_w<3, 4, 32><<<(R_ * 1 * 2 * 32 * 72 + 255) / 256, 256>>>(w1, w1img);
    prep_w<32, 32, 64><<<(R_ * 5 * 2 * 64 * 72 + 255) / 256, 256>>>(w2, w2img);
    prep_w<64, 64, 128><<<(R_ * 9 * 2 * 128 * 72 + 255) / 256, 256>>>(w3, w3img);

    // smem: STAGES * (2*18432 + 2*COUT*144)
    const int SM1 = 1 * (36864 + 2 * 32 * 144);   //  46080
    const int SM2 = 2 * (36864 + 2 * 64 * 144);   // 110592 -> 2 CTAs/SM
    const int SM3 = SM2;                          // conv3 N-split -> same
    cudaFuncSetAttribute(conv_mma6<4, 2, 32, 32, 128, 7, 8, 1, true, false, 1>,
                         cudaFuncAttributeMaxDynamicSharedMemorySize, SM1);
    cudaFuncSetAttribute(conv_mma6<32, 5, 64, 64, 64, 6, 4, 2, false, false, 2>,
                         cudaFuncAttributeMaxDynamicSharedMemorySize, SM2);
    cudaFuncSetAttribute(conv_mma6<64, 6, 64, 128, 32, 5, 4, 2, false, true, 2>,
                         cudaFuncAttributeMaxDynamicSharedMemorySize, SM3);

    // conv1: 16384 px -> 128 tiles
    conv_mma6<4, 2, 32, 32, 128, 7, 8, 1, true, false, 1>
        <<<dim3(128, 1, B_), 256, SM1>>>(
        imgh, imgl, w1img, b1, region, nullptr, b1h, b1l);
    // conv2: 4096 px -> 32 tiles
    conv_mma6<32, 5, 64, 64, 64, 6, 4, 2, false, false, 2>
        <<<dim3(32, 1, B_), 256, SM2>>>(
        b1h, b1l, w2img, b2, region, nullptr, b2h, b2l);
    // conv3: 1024 px -> 8 tiles x 2 N-halves -> fp32 NHWC
    conv_mma6<64, 6, 64, 128, 32, 5, 4, 2, false, true, 2>
        <<<dim3(8, 2, B_), 256, SM3>>>(
        b2h, b2l, w3img, b3, region, buf3, nullptr, nullptr);

    gap_part<<<dim3(8, B_), 128>>>(buf3, part);
    fc_k<<<B_, 128>>>(part, fw, fb, region, out);
}

// round 14
// speedup vs baseline: 1.6270x; 1.0491x over previous
#include <cuda_runtime.h>
#include <cuda_bf16.h>
#include <cstdint>

// ---------------------------------------------------------------------------
// RegionModel round-14: R12 base (im2col smem, 144B pitch, ldmatrix, 2-slot
// cp.async pipeline, 2 CTAs/SM for conv2/conv3) plus:
//  - single fused prep kernel (image split + all weight images)
//  - GAP fused into conv3 epilogue (deterministic tree reduction, no buf3)
// conv1 A-staging stays on the proven 8B cp.async path (16B source would be
// misaligned: odd-pixel NHWC4 offsets are only 8B-aligned).
// Split-bf16 3-term fp32 emulation (Ah*Bh + Ah*Bl + Al*Bh), NHWC hi/lo planes.
// ---------------------------------------------------------------------------

#define B_ 128
#define R_ 8

typedef unsigned int u32;
typedef unsigned long long u64;
typedef unsigned short u16;

// Activations (device globals)
__device__ __align__(16) __nv_bfloat16 g_imgh[(size_t)B_ * 256 * 256 * 4];
__device__ __align__(16) __nv_bfloat16 g_imgl[(size_t)B_ * 256 * 256 * 4];
__device__ __align__(16) __nv_bfloat16 g_b1h[(size_t)B_ * 128 * 128 * 32];
__device__ __align__(16) __nv_bfloat16 g_b1l[(size_t)B_ * 128 * 128 * 32];
__device__ __align__(16) __nv_bfloat16 g_b2h[(size_t)B_ * 64 * 64 * 64];
__device__ __align__(16) __nv_bfloat16 g_b2l[(size_t)B_ * 64 * 64 * 64];
__device__ float g_part[B_ * 8 * 128];
// Weight images: [R][NC][hi|lo][NTOT][72 u16], k = tap*CINP + ci, zero-padded
__device__ __align__(16) __nv_bfloat16 g_w1img[R_ * 1 * 2 * 32 * 72];
__device__ __align__(16) __nv_bfloat16 g_w2img[R_ * 5 * 2 * 64 * 72];
__device__ __align__(16) __nv_bfloat16 g_w3img[R_ * 9 * 2 * 128 * 72];

__device__ __forceinline__ u32 smem_u32(const void* p) {
    u32 a;
    asm("{ .reg .u64 t; cvta.to.shared.u64 t, %1; cvt.u32.u64 %0, t; }"
        : "=r"(a) : "l"(p));
    return a;
}
#define CP16(dst, src) \
    asm volatile("cp.async.cg.shared.global [%0], [%1], 16;" :: "r"(dst), "l"(src))
#define CP16Z(dst, src, sz) \
    asm volatile("cp.async.cg.shared.global [%0], [%1], 16, %2;" \
                 :: "r"(dst), "l"(src), "r"(sz))
#define CP8Z(dst, src, sz) \
    asm volatile("cp.async.ca.shared.global [%0], [%1], 8, %2;" \
                 :: "r"(dst), "l"(src), "r"(sz))
#define CP_COMMIT() asm volatile("cp.async.commit_group;" ::: "memory")
#define CP_WAIT0()  asm volatile("cp.async.wait_group 0;" ::: "memory")
#define CP_WAIT1()  asm volatile("cp.async.wait_group 1;" ::: "memory")
#define LDSM4(r, a) \
    asm volatile("ldmatrix.sync.aligned.m8n8.x4.shared.b16 {%0,%1,%2,%3}, [%4];" \
                 : "=r"((r)[0]), "=r"((r)[1]), "=r"((r)[2]), "=r"((r)[3]) : "r"(a))
#define MMA(acc, af, b0, b1) \
    asm volatile( \
        "mma.sync.aligned.m16n8k16.row.col.f32.bf16.bf16.f32 " \
        "{%0,%1,%2,%3}, {%4,%5,%6,%7}, {%8,%9}, {%0,%1,%2,%3};" \
        : "+f"((acc)[0]), "+f"((acc)[1]), "+f"((acc)[2]), "+f"((acc)[3]) \
        : "r"((af)[0]), "r"((af)[1]), "r"((af)[2]), "r"((af)[3]), "r"(b0), "r"(b1))

// ---------------------------------------------------------------------------
// Fused prep: image split + all 3 weight images, partitioned by blockIdx.x.
// All weight layouts: k = tap*CINP + ci (conv1 CINP=4, ci=3 pad -> 0).
// ---------------------------------------------------------------------------
#define NB_IMG 32768
#define NB_W1  144
#define NB_W2  1800
#define NB_W3  5184

__device__ __forceinline__ void prep_w_body(
    const float* __restrict__ W, __nv_bfloat16* __restrict__ img,
    int idx, int CIN, int CINP, int COUT, int NC)
{
    const int KP = 9 * CINP;
    if (idx >= R_ * NC * 2 * COUT * 72) return;
    const int kl = idx % 72;
    int t = idx / 72;
    const int n  = t % COUT; t /= COUT;
    const int hl = t % 2;    t /= 2;
    const int c  = t % NC;
    const int r  = t / NC;
    __nv_bfloat16 ob = __float2bfloat16_rn(0.0f);
    const int k = c * 64 + kl;
    if (kl < 64 && k < KP) {
        const int tap = k / CINP, ci = k % CINP;
        if (tap < 9 && ci < CIN) {
            const float w = W[(((size_t)r * COUT + n) * CIN + ci) * 9 + tap];
            const __nv_bfloat16 h = __float2bfloat16_rn(w);
            ob = hl ? __float2bfloat16_rn(w - __bfloat162float(h)) : h;
        }
    }
    img[idx] = ob;
}

__global__ void __launch_bounds__(256) prep_all(
    const float* __restrict__ img,
    __nv_bfloat16* __restrict__ oh, __nv_bfloat16* __restrict__ ol,
    const float* __restrict__ w1, __nv_bfloat16* __restrict__ w1img,
    const float* __restrict__ w2, __nv_bfloat16* __restrict__ w2img,
    const float* __restrict__ w3, __nv_bfloat16* __restrict__ w3img)
{
    const int bx = blockIdx.x;
    if (bx < NB_IMG) {
        const int idx = bx * 256 + threadIdx.x;
        const int b = idx >> 16, p = idx & 65535;
        const float* ip = img + (size_t)b * 3 * 65536 + p;
        u16 h[4], l[4];
#pragma unroll
        for (int c = 0; c < 3; c++) {
            const float x = __ldg(ip + (size_t)c * 65536);
            const __nv_bfloat16 hb = __float2bfloat16_rn(x);
            h[c] = __bfloat16_as_ushort(hb);
            l[c] = __bfloat16_as_ushort(__float2bfloat16_rn(x - __bfloat162float(hb)));
        }
        h[3] = 0; l[3] = 0;
        ((u64*)oh)[idx] = *(const u64*)h;
        ((u64*)ol)[idx] = *(const u64*)l;
    } else if (bx < NB_IMG + NB_W1) {
        prep_w_body(w1, w1img, (bx - NB_IMG) * 256 + threadIdx.x, 3, 4, 32, 1);
    } else if (bx < NB_IMG + NB_W1 + NB_W2) {
        prep_w_body(w2, w2img, (bx - NB_IMG - NB_W1) * 256 + threadIdx.x,
                    32, 32, 64, 5);
    } else {
        prep_w_body(w3, w3img, (bx - NB_IMG - NB_W1 - NB_W2) * 256 + threadIdx.x,
                    64, 64, 128, 9);
    }
}

// ---------------------------------------------------------------------------
// Implicit-GEMM conv. grid = (HOUT*HOUT/128, NTOT/COUT, B). 256 threads,
// WM x WN warp grid. Slot: A hi|lo im2col [128x72 u16, 144B pitch] + B hi|lo.
// GAP: epilogue reduces over pixels into part[b][tile][n] (no NHWC output).
// ---------------------------------------------------------------------------
template <int CINP, int LOGC, int COUT, int NTOT, int HOUT, int LOGH,
          int WM, int WN, bool FIRST, bool GAP, int STAGES>
__global__ void __launch_bounds__(256) conv_mma7(
    const __nv_bfloat16* __restrict__ src_h, const __nv_bfloat16* __restrict__ src_l,
    const __nv_bfloat16* __restrict__ wimg, const float* __restrict__ Bias,
    const int* __restrict__ region, float* __restrict__ part,
    __nv_bfloat16* __restrict__ out_h, __nv_bfloat16* __restrict__ out_l)
{
    constexpr int HIN  = 2 * HOUT;
    constexpr int KP   = 9 * CINP;
    constexpr int NC   = (KP + 63) / 64;
    constexpr int MF   = 128 / (16 * WM);
    constexpr int NF   = COUT / (8 * WN);
    constexpr int SSB  = 2 * 18432 + 2 * COUT * 144;   // slot bytes

    extern __shared__ __align__(16) char sm[];

    const int tid = threadIdx.x, lane = tid & 31, wid = tid >> 5;
    const int b   = blockIdx.z;
    const int px0 = blockIdx.x * 128;
    const int n0  = blockIdx.y * COUT;
    const int r   = region[b] & (R_ - 1);
    const int g   = lane >> 2, tc = lane & 3;
    const int wm  = wid & (WM - 1), wn = wid / WM;
    const int M0  = wm * (128 / WM);
    const int N0  = wn * (COUT / WN);

    const int al_off = ((lane & 7) + ((lane >> 3) & 1) * 8) * 144 + (lane >> 4) * 16;
    const int bl_off = ((lane & 7) + ((lane >> 4) & 1) * 8) * 144
                     + ((lane >> 3) & 1) * 16;

    float acc[MF][NF][4];
#pragma unroll
    for (int mf = 0; mf < MF; mf++)
#pragma unroll
        for (int nf = 0; nf < NF; nf++)
            acc[mf][nf][0] = acc[mf][nf][1] = acc[mf][nf][2] = acc[mf][nf][3] = 0.f;

    const __nv_bfloat16* wr = wimg + (size_t)r * NC * 2 * NTOT * 72;

    auto stage = [&](int c, int s) {
        char* sb = sm + s * SSB;
        const u32 au = smem_u32(sb);
        const u32 bu = au + 2 * 18432;
        const u16* src = (const u16*)wr + (size_t)c * 2 * NTOT * 72;
        for (int i = tid; i < 2 * COUT * 9; i += 256) {
            const int half = i / (COUT * 9);
            const int rem  = i - half * COUT * 9;
            const int row  = rem / 9, u = rem - row * 9;
            const u16* sp = src + (size_t)half * NTOT * 72 + (n0 + row) * 72 + u * 8;
            CP16(bu + half * COUT * 144 + row * 144 + u * 16, sp);
        }
        if (FIRST) {
            // CINP=4: k = tap*4 + ci; q = tap; zero rows q 9..11 (8B aligned)
            for (int i = tid; i < 2048; i += 256) {
                const int m = i >> 4, q = i & 15;
                if (q >= 12) continue;
                if (q < 9) {
                    const int px = px0 + m;
                    const int oy = px >> LOGH, ox = px & (HOUT - 1);
                    const int ty = q / 3, tx2 = q - 3 * ty;
                    const int iy = 2 * oy + ty - 1, ix = 2 * ox + tx2 - 1;
                    const bool v = (unsigned)iy < (unsigned)HIN &&
                                   (unsigned)ix < (unsigned)HIN;
                    const size_t off = v ? (((size_t)(b * HIN + iy) * HIN + ix) * 4) : 0;
                    const int sz = v ? 8 : 0;
                    const u32 d = au + m * 144 + q * 8;
                    CP8Z(d, src_h + off, sz);
                    CP8Z(d + 18432, src_l + off, sz);
                } else {
                    *(u64*)(sb + m * 144 + q * 8) = 0;
                    *(u64*)(sb + 18432 + m * 144 + q * 8) = 0;
                }
            }
        } else {
            for (int i = tid; i < 1024; i += 256) {
                const int m = i >> 3, q = i & 7;
                const int k = c * 64 + q * 8;
                if (k >= KP) continue;
                const int tap = k >> LOGC, ci0 = k & (CINP - 1);
                const int ty = tap / 3, tx2 = tap - 3 * ty;
                const int px = px0 + m;
                const int oy = px >> LOGH, ox = px & (HOUT - 1);
                const int iy = 2 * oy + ty - 1, ix = 2 * ox + tx2 - 1;
                const bool v = (unsigned)iy < (unsigned)HIN &&
                               (unsigned)ix < (unsigned)HIN;
                const size_t off = v
                    ? (((size_t)(b * HIN + iy) * HIN + ix) * CINP + ci0) : 0;
                const int sz = v ? 16 : 0;
                const u32 d = au + m * 144 + q * 16;
                CP16Z(d, src_h + off, sz);
                CP16Z(d + 18432, src_l + off, sz);
            }
        }
        CP_COMMIT();
    };

    auto domma = [&](int c, int s) {
        const int rem = KP - c * 64;
        const int nks = (rem >= 64) ? 4 : ((rem + 15) >> 4);
        const u32 au  = smem_u32(sm + s * SSB);
        const u32 Ahi = au, Alo = au + 18432;
        const u32 Bhi = au + 2 * 18432, Blo = Bhi + COUT * 144;
#pragma unroll 4
        for (int ks = 0; ks < nks; ks++) {
            const int kb = ks * 32;
            u32 bfh[NF / 2][4], bfl[NF / 2][4];
#pragma unroll
            for (int np = 0; np < NF / 2; np++) {
                LDSM4(bfh[np], Bhi + (N0 + np * 16) * 144 + kb + bl_off);
                LDSM4(bfl[np], Blo + (N0 + np * 16) * 144 + kb + bl_off);
            }
            u32 af[MF][4];
#pragma unroll
            for (int mf = 0; mf < MF; mf++)
                LDSM4(af[mf], Ahi + (M0 + mf * 16) * 144 + kb + al_off);
#pragma unroll
            for (int mf = 0; mf < MF; mf++)
#pragma unroll
                for (int nf = 0; nf < NF; nf++) {
                    const u32 b0h = bfh[nf >> 1][(nf & 1) ? 2 : 0];
                    const u32 b1h = bfh[nf >> 1][(nf & 1) ? 3 : 1];
                    const u32 b0l = bfl[nf >> 1][(nf & 1) ? 2 : 0];
                    const u32 b1l = bfl[nf >> 1][(nf & 1) ? 3 : 1];
                    MMA(acc[mf][nf], af[mf], b0h, b1h);
                    MMA(acc[mf][nf], af[mf], b0l, b1l);
                }
#pragma unroll
            for (int mf = 0; mf < MF; mf++)
                LDSM4(af[mf], Alo + (M0 + mf * 16) * 144 + kb + al_off);
#pragma unroll
            for (int mf = 0; mf < MF; mf++)
#pragma unroll
                for (int nf = 0; nf < NF; nf++) {
                    const u32 b0h = bfh[nf >> 1][(nf & 1) ? 2 : 0];
                    const u32 b1h = bfh[nf >> 1][(nf & 1) ? 3 : 1];
                    MMA(acc[mf][nf], af[mf], b0h, b1h);
                }
        }
    };

    // ---- pipeline: 2 slots, stage-distance 2 ----
    stage(0, 0);
    if (STAGES > 1 && NC > 1) stage(1, 1);
    for (int c = 0; c < NC; c++) {
        if (STAGES > 1 && c + 1 < NC) { CP_WAIT1(); } else { CP_WAIT0(); }
        __syncthreads();
        domma(c, (STAGES > 1) ? (c & 1) : 0);
        if (STAGES > 1) {
            __syncthreads();
            if (c + 2 < NC) stage(c + 2, c & 1);
        }
    }

    // ---- epilogue ----
    const float* bias_g = Bias + r * NTOT + n0;
    if (GAP) {
        // bias + ReLU + per-thread pixel sums, then deterministic reduction
        float s0[NF], s1[NF];
#pragma unroll
        for (int nf = 0; nf < NF; nf++) { s0[nf] = 0.f; s1[nf] = 0.f; }
#pragma unroll
        for (int mf = 0; mf < MF; mf++)
#pragma unroll
            for (int half = 0; half < 2; half++)
#pragma unroll
                for (int nf = 0; nf < NF; nf++) {
                    const int n = N0 + nf * 8 + tc * 2;
                    s0[nf] += fmaxf(acc[mf][nf][half * 2 + 0] + __ldg(bias_g + n), 0.f);
                    s1[nf] += fmaxf(acc[mf][nf][half * 2 + 1] + __ldg(bias_g + n + 1), 0.f);
                }
        // reduce over g (lanes differing in bits 2..4)
#pragma unroll
        for (int o = 16; o >= 4; o >>= 1)
#pragma unroll
            for (int nf = 0; nf < NF; nf++) {
                s0[nf] += __shfl_down_sync(0xFFFFFFFFu, s0[nf], o);
                s1[nf] += __shfl_down_sync(0xFFFFFFFFu, s1[nf], o);
            }
        __syncthreads();                       // safe to reuse slot smem
        float* red = (float*)sm;               // [8 warps][NF][8]
        if (lane < 4)
#pragma unroll
            for (int nf = 0; nf < NF; nf++) {
                red[(wid * NF + nf) * 8 + tc * 2 + 0] = s0[nf];
                red[(wid * NF + nf) * 8 + tc * 2 + 1] = s1[nf];
            }
        __syncthreads();
        if (tid < WN * NF * 8) {
            const int wn2 = tid / (NF * 8);
            const int rem = tid - wn2 * NF * 8;
            const int nf = rem >> 3, j = rem & 7;
            float t = 0.f;
#pragma unroll
            for (int w2 = 0; w2 < WM; w2++)
                t += red[((wn2 * WM + w2) * NF + nf) * 8 + j];
            const int n = n0 + wn2 * (COUT / WN) + nf * 8 + j;
            part[((size_t)b * 8 + blockIdx.x) * 128 + n] = t;
        }
    } else {
#pragma unroll
        for (int mf = 0; mf < MF; mf++)
#pragma unroll
            for (int half = 0; half < 2; half++) {
                const int m  = M0 + mf * 16 + g + half * 8;
                const int px = px0 + m;
                const int oy = px >> LOGH, ox = px & (HOUT - 1);
                const size_t base = (((size_t)b * HOUT + oy) * HOUT + ox) * NTOT + n0;
#pragma unroll
                for (int nf = 0; nf < NF; nf++) {
                    const int n = N0 + nf * 8 + tc * 2;
                    const float y0 = fmaxf(acc[mf][nf][half * 2 + 0] + __ldg(bias_g + n), 0.f);
                    const float y1 = fmaxf(acc[mf][nf][half * 2 + 1] + __ldg(bias_g + n + 1), 0.f);
                    const __nv_bfloat16 h0 = __float2bfloat16_rn(y0);
                    const __nv_bfloat16 h1 = __float2bfloat16_rn(y1);
                    const __nv_bfloat16 l0 = __float2bfloat16_rn(y0 - __bfloat162float(h0));
                    const __nv_bfloat16 l1 = __float2bfloat16_rn(y1 - __bfloat162float(h1));
                    *(u32*)(out_h + base + n) =
                        (u32)__bfloat16_as_ushort(h0) | ((u32)__bfloat16_as_ushort(h1) << 16);
                    *(u32*)(out_l + base + n) =
                        (u32)__bfloat16_as_ushort(l0) | ((u32)__bfloat16_as_ushort(l1) << 16);
                }
            }
    }
}

// ---------------------------------------------------------------------------
__global__ void __launch_bounds__(128) fc_k(const float* __restrict__ part,
                                            const float* __restrict__ fw,
                                            const float* __restrict__ fb,
                                            const int* __restrict__ region,
                                            float* __restrict__ out)
{
    __shared__ float f[128];
    const int b = blockIdx.x, tid = threadIdx.x;
    const int r = region[b] & (R_ - 1);
    float s = 0.0f;
#pragma unroll
    for (int q = 0; q < 8; q++) s += part[(b * 8 + q) * 128 + tid];
    f[tid] = s * (1.0f / 1024.0f);
    __syncthreads();
    if (tid < 32) {
        const float* w0 = fw + ((size_t)r * 2 + 0) * 128;
        const float* w1 = fw + ((size_t)r * 2 + 1) * 128;
        float p0 = 0.0f, p1 = 0.0f;
#pragma unroll
        for (int i = tid; i < 128; i += 32) {
            p0 = fmaf(f[i], w0[i], p0);
            p1 = fmaf(f[i], w1[i], p1);
        }
#pragma unroll
        for (int o = 16; o > 0; o >>= 1) {
            p0 += __shfl_down_sync(0xFFFFFFFFu, p0, o);
            p1 += __shfl_down_sync(0xFFFFFFFFu, p1, o);
        }
        if (tid == 0) {
            out[b * 2 + 0] = p0 + fb[r * 2 + 0];
            out[b * 2 + 1] = p1 + fb[r * 2 + 1];
        }
    }
}

// ---------------------------------------------------------------------------
extern "C" void kernel_launch(void* const* d_in, const int* in_sizes, int n_in,
                              void* d_out, int out_size)
{
    const float* image  = (const float*)d_in[0];
    const int*   region = (const int*)d_in[1];
    const float* w1     = (const float*)d_in[2];
    const float* b1     = (const float*)d_in[3];
    const float* w2     = (const float*)d_in[4];
    const float* b2     = (const float*)d_in[5];
    const float* w3     = (const float*)d_in[6];
    const float* b3     = (const float*)d_in[7];
    const float* fw     = (const float*)d_in[8];
    const float* fb     = (const float*)d_in[9];
    float* out = (float*)d_out;

    __nv_bfloat16 *imgh, *imgl, *b1h, *b1l, *b2h, *b2l, *w1img, *w2img, *w3img;
    float *part;
    cudaGetSymbolAddress((void**)&imgh, g_imgh);
    cudaGetSymbolAddress((void**)&imgl, g_imgl);
    cudaGetSymbolAddress((void**)&b1h, g_b1h);
    cudaGetSymbolAddress((void**)&b1l, g_b1l);
    cudaGetSymbolAddress((void**)&b2h, g_b2h);
    cudaGetSymbolAddress((void**)&b2l, g_b2l);
    cudaGetSymbolAddress((void**)&part, g_part);
    cudaGetSymbolAddress((void**)&w1img, g_w1img);
    cudaGetSymbolAddress((void**)&w2img, g_w2img);
    cudaGetSymbolAddress((void**)&w3img, g_w3img);

    // One fused prep launch
    prep_all<<<NB_IMG + NB_W1 + NB_W2 + NB_W3, 256>>>(
        image, imgh, imgl, w1, w1img, w2, w2img, w3, w3img);

    // smem: STAGES * (2*18432 + 2*COUT*144)
    const int SM1 = 1 * (36864 + 2 * 32 * 144);   //  46080
    const int SM2 = 2 * (36864 + 2 * 64 * 144);   // 110592 -> 2 CTAs/SM
    const int SM3 = SM2;
    cudaFuncSetAttribute(conv_mma7<4, 2, 32, 32, 128, 7, 8, 1, true, false, 1>,
                         cudaFuncAttributeMaxDynamicSharedMemorySize, SM1);
    cudaFuncSetAttribute(conv_mma7<32, 5, 64, 64, 64, 6, 4, 2, false, false, 2>,
                         cudaFuncAttributeMaxDynamicSharedMemorySize, SM2);
    cudaFuncSetAttribute(conv_mma7<64, 6, 64, 128, 32, 5, 4, 2, false, true, 2>,
                         cudaFuncAttributeMaxDynamicSharedMemorySize, SM3);

    // conv1: 16384 px -> 128 tiles
    conv_mma7<4, 2, 32, 32, 128, 7, 8, 1, true, false, 1>
        <<<dim3(128, 1, B_), 256, SM1>>>(
        imgh, imgl, w1img, b1, region, nullptr, b1h, b1l);
    // conv2: 4096 px -> 32 tiles
    conv_mma7<32, 5, 64, 64, 64, 6, 4, 2, false, false, 2>
        <<<dim3(32, 1, B_), 256, SM2>>>(
        b1h, b1l, w2img, b2, region, nullptr, b2h, b2l);
    // conv3: 8 tiles x 2 N-halves, GAP fused -> part[b][tile][128]
    conv_mma7<64, 6, 64, 128, 32, 5, 4, 2, false, true, 2>
        <<<dim3(8, 2, B_), 256, SM3>>>(
        b2h, b2l, w3img, b3, region, part, nullptr, nullptr);

    fc_k<<<B_, 128>>>(part, fw, fb, region, out);
}

// round 15
// speedup vs baseline: 1.7775x; 1.0925x over previous
#include <cuda_runtime.h>
#include <cuda_bf16.h>
#include <cstdint>

// ---------------------------------------------------------------------------
// RegionModel round-15: hybrid.
//  conv1: direct-from-tile (R11 FIRST path) — input tile staged once per
//         block (9 rows x 260 px x 4ch, hi/lo), ldmatrix straight from the
//         tile (16B row spacing = conflict-free at CINP=4), KP=48 weights
//         (k = ty*16 + tx*4 + ci, pad -> zero weights).
//  conv2/conv3: R14 im2col kernels (144B pitch, 2-slot cp.async pipeline,
//         2 CTAs/SM, conv3 N-split + fused GAP).
// Split-bf16 3-term fp32 emulation (Ah*Bh + Ah*Bl + Al*Bh), NHWC hi/lo planes.
// ---------------------------------------------------------------------------

#define B_ 128
#define R_ 8

typedef unsigned int u32;
typedef unsigned long long u64;
typedef unsigned short u16;

// Activations (device globals)
__device__ __align__(16) __nv_bfloat16 g_imgh[(size_t)B_ * 256 * 256 * 4];
__device__ __align__(16) __nv_bfloat16 g_imgl[(size_t)B_ * 256 * 256 * 4];
__device__ __align__(16) __nv_bfloat16 g_b1h[(size_t)B_ * 128 * 128 * 32];
__device__ __align__(16) __nv_bfloat16 g_b1l[(size_t)B_ * 128 * 128 * 32];
__device__ __align__(16) __nv_bfloat16 g_b2h[(size_t)B_ * 64 * 64 * 64];
__device__ __align__(16) __nv_bfloat16 g_b2l[(size_t)B_ * 64 * 64 * 64];
__device__ float g_part[B_ * 8 * 128];
// Weight images: w1: [R][hi|lo][32][72] (k=ty*16+tx*4+ci, KP=48)
//                w2/w3: [R][NC][hi|lo][NTOT][72] (k=tap*CINP+ci)
__device__ __align__(16) __nv_bfloat16 g_w1img[R_ * 2 * 32 * 72];
__device__ __align__(16) __nv_bfloat16 g_w2img[R_ * 5 * 2 * 64 * 72];
__device__ __align__(16) __nv_bfloat16 g_w3img[R_ * 9 * 2 * 128 * 72];

__device__ __forceinline__ u32 smem_u32(const void* p) {
    u32 a;
    asm("{ .reg .u64 t; cvta.to.shared.u64 t, %1; cvt.u32.u64 %0, t; }"
        : "=r"(a) : "l"(p));
    return a;
}
#define CP16(dst, src) \
    asm volatile("cp.async.cg.shared.global [%0], [%1], 16;" :: "r"(dst), "l"(src))
#define CP16Z(dst, src, sz) \
    asm volatile("cp.async.cg.shared.global [%0], [%1], 16, %2;" \
                 :: "r"(dst), "l"(src), "r"(sz))
#define CP8Z(dst, src, sz) \
    asm volatile("cp.async.ca.shared.global [%0], [%1], 8, %2;" \
                 :: "r"(dst), "l"(src), "r"(sz))
#define CP_COMMIT() asm volatile("cp.async.commit_group;" ::: "memory")
#define CP_WAIT0()  asm volatile("cp.async.wait_group 0;" ::: "memory")
#define CP_WAIT1()  asm volatile("cp.async.wait_group 1;" ::: "memory")
#define LDSM4(r, a) \
    asm volatile("ldmatrix.sync.aligned.m8n8.x4.shared.b16 {%0,%1,%2,%3}, [%4];" \
                 : "=r"((r)[0]), "=r"((r)[1]), "=r"((r)[2]), "=r"((r)[3]) : "r"(a))
#define MMA(acc, af, b0, b1) \
    asm volatile( \
        "mma.sync.aligned.m16n8k16.row.col.f32.bf16.bf16.f32 " \
        "{%0,%1,%2,%3}, {%4,%5,%6,%7}, {%8,%9}, {%0,%1,%2,%3};" \
        : "+f"((acc)[0]), "+f"((acc)[1]), "+f"((acc)[2]), "+f"((acc)[3]) \
        : "r"((af)[0]), "r"((af)[1]), "r"((af)[2]), "r"((af)[3]), "r"(b0), "r"(b1))

// ---------------------------------------------------------------------------
// Fused prep: image split + all 3 weight images, partitioned by blockIdx.x.
// ---------------------------------------------------------------------------
#define NB_IMG 32768
#define NB_W1  144
#define NB_W2  1800
#define NB_W3  5184

__device__ __forceinline__ void prep_w_body(
    const float* __restrict__ W, __nv_bfloat16* __restrict__ img,
    int idx, int CIN, int CINP, int COUT, int NC)
{
    const int KP = 9 * CINP;
    if (idx >= R_ * NC * 2 * COUT * 72) return;
    const int kl = idx % 72;
    int t = idx / 72;
    const int n  = t % COUT; t /= COUT;
    const int hl = t % 2;    t /= 2;
    const int c  = t % NC;
    const int r  = t / NC;
    __nv_bfloat16 ob = __float2bfloat16_rn(0.0f);
    const int k = c * 64 + kl;
    if (kl < 64 && k < KP) {
        const int tap = k / CINP, ci = k % CINP;
        if (tap < 9 && ci < CIN) {
            const float w = W[(((size_t)r * COUT + n) * CIN + ci) * 9 + tap];
            const __nv_bfloat16 h = __float2bfloat16_rn(w);
            ob = hl ? __float2bfloat16_rn(w - __bfloat162float(h)) : h;
        }
    }
    img[idx] = ob;
}

__global__ void __launch_bounds__(256) prep_all(
    const float* __restrict__ img,
    __nv_bfloat16* __restrict__ oh, __nv_bfloat16* __restrict__ ol,
    const float* __restrict__ w1, __nv_bfloat16* __restrict__ w1img,
    const float* __restrict__ w2, __nv_bfloat16* __restrict__ w2img,
    const float* __restrict__ w3, __nv_bfloat16* __restrict__ w3img)
{
    const int bx = blockIdx.x;
    if (bx < NB_IMG) {
        const int idx = bx * 256 + threadIdx.x;
        const int b = idx >> 16, p = idx & 65535;
        const float* ip = img + (size_t)b * 3 * 65536 + p;
        u16 h[4], l[4];
#pragma unroll
        for (int c = 0; c < 3; c++) {
            const float x = __ldg(ip + (size_t)c * 65536);
            const __nv_bfloat16 hb = __float2bfloat16_rn(x);
            h[c] = __bfloat16_as_ushort(hb);
            l[c] = __bfloat16_as_ushort(__float2bfloat16_rn(x - __bfloat162float(hb)));
        }
        h[3] = 0; l[3] = 0;
        ((u64*)oh)[idx] = *(const u64*)h;
        ((u64*)ol)[idx] = *(const u64*)l;
    } else if (bx < NB_IMG + NB_W1) {
        // conv1: k = ty*16 + tx*4 + ci (tx=3 / ci=3 pads -> 0), KP=48
        const int idx = (bx - NB_IMG) * 256 + threadIdx.x;
        if (idx >= R_ * 2 * 32 * 72) return;
        const int kl = idx % 72;
        int t = idx / 72;
        const int n  = t % 32; t /= 32;
        const int hl = t % 2;
        const int r  = t / 2;
        __nv_bfloat16 ob = __float2bfloat16_rn(0.0f);
        if (kl < 48) {
            const int ty = kl >> 4, rem = kl & 15, tx = rem >> 2, ci = rem & 3;
            if (tx < 3 && ci < 3) {
                const float w = w1[(((size_t)r * 32 + n) * 3 + ci) * 9 + ty * 3 + tx];
                const __nv_bfloat16 h = __float2bfloat16_rn(w);
                ob = hl ? __float2bfloat16_rn(w - __bfloat162float(h)) : h;
            }
        }
        w1img[idx] = ob;
    } else if (bx < NB_IMG + NB_W1 + NB_W2) {
        prep_w_body(w2, w2img, (bx - NB_IMG - NB_W1) * 256 + threadIdx.x,
                    32, 32, 64, 5);
    } else {
        prep_w_body(w3, w3img, (bx - NB_IMG - NB_W1 - NB_W2) * 256 + threadIdx.x,
                    64, 64, 128, 9);
    }
}

// ---------------------------------------------------------------------------
// conv1: direct-from-tile. grid = (32, 1, B). 256 threads, WM=8 x WN=1.
// Block: 4 output rows (M=512). Tile: 9 rows x 260 px x 4ch, hi+lo planes
// (tile col t <-> ix = t-1). KP=48, 3 k-steps. Outputs NHWC bf16 hi/lo.
// ---------------------------------------------------------------------------
__global__ void __launch_bounds__(256) conv1_k(
    const __nv_bfloat16* __restrict__ src_h, const __nv_bfloat16* __restrict__ src_l,
    const __nv_bfloat16* __restrict__ wimg, const float* __restrict__ Bias,
    const int* __restrict__ region,
    __nv_bfloat16* __restrict__ out_h, __nv_bfloat16* __restrict__ out_l)
{
    constexpr int HIN = 256, HOUT = 128;
    constexpr int ROWW = 260;
    constexpr int APLANE = 9 * ROWW * 4 * 2;     // 18720 B per plane
    constexpr int MF = 4, NF = 4;

    extern __shared__ __align__(16) char sm[];
    const u32 Au = smem_u32(sm);
    const u32 Bhi = Au + 2 * APLANE;
    const u32 Blo = Bhi + 32 * 144;

    const int tid = threadIdx.x, lane = tid & 31, wid = tid >> 5;
    const int b   = blockIdx.z;
    const int r   = region[b] & (R_ - 1);
    const int oy0 = blockIdx.x * 4;
    const int iy0 = 8 * blockIdx.x - 1;
    const int g   = lane >> 2, tc = lane & 3;
    const int M0  = wid * 64;
    const int khalf = lane >> 4;
    const int mrow16 = (lane & 7) + ((lane >> 3) & 1) * 8;

    int rowb[MF], jb[MF];
#pragma unroll
    for (int mf = 0; mf < MF; mf++) {
        const int m = M0 + mf * 16 + mrow16;
        rowb[mf] = 2 * (m >> 7);
        jb[mf]   = 2 * (m & 127);
    }
    const int bl_off = ((lane & 7) + ((lane >> 4) & 1) * 8) * 144
                     + ((lane >> 3) & 1) * 16;

    float acc[MF][NF][4];
#pragma unroll
    for (int mf = 0; mf < MF; mf++)
#pragma unroll
        for (int nf = 0; nf < NF; nf++)
            acc[mf][nf][0] = acc[mf][nf][1] = acc[mf][nf][2] = acc[mf][nf][3] = 0.f;

    // ---- stage input tile (both planes) + B once ----
    {
        constexpr int UA8 = 9 * ROWW;
        for (int i = tid; i < 2 * UA8; i += 256) {
            const int pl = (i >= UA8);
            const int u  = i - pl * UA8;
            const int rr = u / ROWW, t = u - rr * ROWW;
            const int iy = iy0 + rr;
            const int ix = t - 1;
            const bool v = ((unsigned)iy < (unsigned)HIN) &&
                           ((unsigned)ix < (unsigned)HIN);
            const size_t off = v ? (((size_t)(b * HIN + iy) * HIN + ix) * 4) : 0;
            const u32 d = Au + pl * APLANE + (rr * ROWW + t) * 8;
            CP8Z(d, (pl ? src_l : src_h) + off, v ? 8 : 0);
        }
        const char* ws = (const char*)(wimg + (size_t)r * 2 * 32 * 72);
        for (int i = tid; i < 2 * 32 * 9; i += 256)
            CP16(Bhi + i * 16, ws + (size_t)i * 16);
    }
    CP_COMMIT();
    CP_WAIT0();
    __syncthreads();

    // ---- MMA: 3 k-steps (ty), 3 terms ----
#pragma unroll
    for (int ks = 0; ks < 3; ks++) {
        const int kb = ks * 32;
        u32 aaddr[MF];
#pragma unroll
        for (int mf = 0; mf < MF; mf++)
            aaddr[mf] = Au + (((rowb[mf] + ks) * ROWW + jb[mf] + khalf * 2) << 3);

        u32 bfh[NF / 2][4], bfl[NF / 2][4];
#pragma unroll
        for (int np = 0; np < NF / 2; np++) {
            LDSM4(bfh[np], Bhi + (np * 16) * 144 + kb + bl_off);
            LDSM4(bfl[np], Blo + (np * 16) * 144 + kb + bl_off);
        }
        u32 af[MF][4];
#pragma unroll
        for (int mf = 0; mf < MF; mf++) LDSM4(af[mf], aaddr[mf]);
#pragma unroll
        for (int mf = 0; mf < MF; mf++)
#pragma unroll
            for (int nf = 0; nf < NF; nf++) {
                const u32 b0h = bfh[nf >> 1][(nf & 1) ? 2 : 0];
                const u32 b1h = bfh[nf >> 1][(nf & 1) ? 3 : 1];
                const u32 b0l = bfl[nf >> 1][(nf & 1) ? 2 : 0];
                const u32 b1l = bfl[nf >> 1][(nf & 1) ? 3 : 1];
                MMA(acc[mf][nf], af[mf], b0h, b1h);
                MMA(acc[mf][nf], af[mf], b0l, b1l);
            }
#pragma unroll
        for (int mf = 0; mf < MF; mf++) LDSM4(af[mf], aaddr[mf] + APLANE);
#pragma unroll
        for (int mf = 0; mf < MF; mf++)
#pragma unroll
            for (int nf = 0; nf < NF; nf++) {
                const u32 b0h = bfh[nf >> 1][(nf & 1) ? 2 : 0];
                const u32 b1h = bfh[nf >> 1][(nf & 1) ? 3 : 1];
                MMA(acc[mf][nf], af[mf], b0h, b1h);
            }
    }

    // ---- epilogue: bias + ReLU -> NHWC bf16 hi/lo ----
    const float* bias_g = Bias + r * 32;
#pragma unroll
    for (int mf = 0; mf < MF; mf++)
#pragma unroll
        for (int half = 0; half < 2; half++) {
            const int m  = M0 + mf * 16 + g + half * 8;
            const int oy = oy0 + (m >> 7), ox = m & 127;
            const size_t base = (((size_t)b * HOUT + oy) * HOUT + ox) * 32;
#pragma unroll
            for (int nf = 0; nf < NF; nf++) {
                const int n = nf * 8 + tc * 2;
                const float y0 = fmaxf(acc[mf][nf][half * 2 + 0] + __ldg(bias_g + n), 0.f);
                const float y1 = fmaxf(acc[mf][nf][half * 2 + 1] + __ldg(bias_g + n + 1), 0.f);
                const __nv_bfloat16 h0 = __float2bfloat16_rn(y0);
                const __nv_bfloat16 h1 = __float2bfloat16_rn(y1);
                const __nv_bfloat16 l0 = __float2bfloat16_rn(y0 - __bfloat162float(h0));
                const __nv_bfloat16 l1 = __float2bfloat16_rn(y1 - __bfloat162float(h1));
                *(u32*)(out_h + base + n) =
                    (u32)__bfloat16_as_ushort(h0) | ((u32)__bfloat16_as_ushort(h1) << 16);
                *(u32*)(out_l + base + n) =
                    (u32)__bfloat16_as_ushort(l0) | ((u32)__bfloat16_as_ushort(l1) << 16);
            }
        }
}

// ---------------------------------------------------------------------------
// conv2/conv3: im2col implicit GEMM (R14). grid=(tiles, NTOT/COUT, B).
// ---------------------------------------------------------------------------
template <int CINP, int LOGC, int COUT, int NTOT, int HOUT, int LOGH,
          int WM, int WN, bool GAP>
__global__ void __launch_bounds__(256) conv_mma7(
    const __nv_bfloat16* __restrict__ src_h, const __nv_bfloat16* __restrict__ src_l,
    const __nv_bfloat16* __restrict__ wimg, const float* __restrict__ Bias,
    const int* __restrict__ region, float* __restrict__ part,
    __nv_bfloat16* __restrict__ out_h, __nv_bfloat16* __restrict__ out_l)
{
    constexpr int HIN  = 2 * HOUT;
    constexpr int KP   = 9 * CINP;
    constexpr int NC   = (KP + 63) / 64;
    constexpr int MF   = 128 / (16 * WM);
    constexpr int NF   = COUT / (8 * WN);
    constexpr int SSB  = 2 * 18432 + 2 * COUT * 144;

    extern __shared__ __align__(16) char sm[];

    const int tid = threadIdx.x, lane = tid & 31, wid = tid >> 5;
    const int b   = blockIdx.z;
    const int px0 = blockIdx.x * 128;
    const int n0  = blockIdx.y * COUT;
    const int r   = region[b] & (R_ - 1);
    const int g   = lane >> 2, tc = lane & 3;
    const int wm  = wid & (WM - 1), wn = wid / WM;
    const int M0  = wm * (128 / WM);
    const int N0  = wn * (COUT / WN);

    const int al_off = ((lane & 7) + ((lane >> 3) & 1) * 8) * 144 + (lane >> 4) * 16;
    const int bl_off = ((lane & 7) + ((lane >> 4) & 1) * 8) * 144
                     + ((lane >> 3) & 1) * 16;

    float acc[MF][NF][4];
#pragma unroll
    for (int mf = 0; mf < MF; mf++)
#pragma unroll
        for (int nf = 0; nf < NF; nf++)
            acc[mf][nf][0] = acc[mf][nf][1] = acc[mf][nf][2] = acc[mf][nf][3] = 0.f;

    const __nv_bfloat16* wr = wimg + (size_t)r * NC * 2 * NTOT * 72;

    auto stage = [&](int c, int s) {
        char* sb = sm + s * SSB;
        const u32 au = smem_u32(sb);
        const u32 bu = au + 2 * 18432;
        const u16* src = (const u16*)wr + (size_t)c * 2 * NTOT * 72;
        for (int i = tid; i < 2 * COUT * 9; i += 256) {
            const int half = i / (COUT * 9);
            const int rem  = i - half * COUT * 9;
            const int row  = rem / 9, u = rem - row * 9;
            const u16* sp = src + (size_t)half * NTOT * 72 + (n0 + row) * 72 + u * 8;
            CP16(bu + half * COUT * 144 + row * 144 + u * 16, sp);
        }
        for (int i = tid; i < 1024; i += 256) {
            const int m = i >> 3, q = i & 7;
            const int k = c * 64 + q * 8;
            if (k >= KP) continue;
            const int tap = k >> LOGC, ci0 = k & (CINP - 1);
            const int ty = tap / 3, tx2 = tap - 3 * ty;
            const int px = px0 + m;
            const int oy = px >> LOGH, ox = px & (HOUT - 1);
            const int iy = 2 * oy + ty - 1, ix = 2 * ox + tx2 - 1;
            const bool v = (unsigned)iy < (unsigned)HIN &&
                           (unsigned)ix < (unsigned)HIN;
            const size_t off = v
                ? (((size_t)(b * HIN + iy) * HIN + ix) * CINP + ci0) : 0;
            const int sz = v ? 16 : 0;
            const u32 d = au + m * 144 + q * 16;
            CP16Z(d, src_h + off, sz);
            CP16Z(d + 18432, src_l + off, sz);
        }
        CP_COMMIT();
    };

    auto domma = [&](int c, int s) {
        const int rem = KP - c * 64;
        const int nks = (rem >= 64) ? 4 : ((rem + 15) >> 4);
        const u32 au  = smem_u32(sm + s * SSB);
        const u32 Ahi = au, Alo = au + 18432;
        const u32 Bhi = au + 2 * 18432, Blo = Bhi + COUT * 144;
#pragma unroll 4
        for (int ks = 0; ks < nks; ks++) {
            const int kb = ks * 32;
            u32 bfh[NF / 2][4], bfl[NF / 2][4];
#pragma unroll
            for (int np = 0; np < NF / 2; np++) {
                LDSM4(bfh[np], Bhi + (N0 + np * 16) * 144 + kb + bl_off);
                LDSM4(bfl[np], Blo + (N0 + np * 16) * 144 + kb + bl_off);
            }
            u32 af[MF][4];
#pragma unroll
            for (int mf = 0; mf < MF; mf++)
                LDSM4(af[mf], Ahi + (M0 + mf * 16) * 144 + kb + al_off);
#pragma unroll
            for (int mf = 0; mf < MF; mf++)
#pragma unroll
                for (int nf = 0; nf < NF; nf++) {
                    const u32 b0h = bfh[nf >> 1][(nf & 1) ? 2 : 0];
                    const u32 b1h = bfh[nf >> 1][(nf & 1) ? 3 : 1];
                    const u32 b0l = bfl[nf >> 1][(nf & 1) ? 2 : 0];
                    const u32 b1l = bfl[nf >> 1][(nf & 1) ? 3 : 1];
                    MMA(acc[mf][nf], af[mf], b0h, b1h);
                    MMA(acc[mf][nf], af[mf], b0l, b1l);
                }
#pragma unroll
            for (int mf = 0; mf < MF; mf++)
                LDSM4(af[mf], Alo + (M0 + mf * 16) * 144 + kb + al_off);
#pragma unroll
            for (int mf = 0; mf < MF; mf++)
#pragma unroll
                for (int nf = 0; nf < NF; nf++) {
                    const u32 b0h = bfh[nf >> 1][(nf & 1) ? 2 : 0];
                    const u32 b1h = bfh[nf >> 1][(nf & 1) ? 3 : 1];
                    MMA(acc[mf][nf], af[mf], b0h, b1h);
                }
        }
    };

    stage(0, 0);
    if (NC > 1) stage(1, 1);
    for (int c = 0; c < NC; c++) {
        if (c + 1 < NC) { CP_WAIT1(); } else { CP_WAIT0(); }
        __syncthreads();
        domma(c, c & 1);
        __syncthreads();
        if (c + 2 < NC) stage(c + 2, c & 1);
    }

    const float* bias_g = Bias + r * NTOT + n0;
    if (GAP) {
        float s0[NF], s1[NF];
#pragma unroll
        for (int nf = 0; nf < NF; nf++) { s0[nf] = 0.f; s1[nf] = 0.f; }
#pragma unroll
        for (int mf = 0; mf < MF; mf++)
#pragma unroll
            for (int half = 0; half < 2; half++)
#pragma unroll
                for (int nf = 0; nf < NF; nf++) {
                    const int n = N0 + nf * 8 + tc * 2;
                    s0[nf] += fmaxf(acc[mf][nf][half * 2 + 0] + __ldg(bias_g + n), 0.f);
                    s1[nf] += fmaxf(acc[mf][nf][half * 2 + 1] + __ldg(bias_g + n + 1), 0.f);
                }
#pragma unroll
        for (int o = 16; o >= 4; o >>= 1)
#pragma unroll
            for (int nf = 0; nf < NF; nf++) {
                s0[nf] += __shfl_down_sync(0xFFFFFFFFu, s0[nf], o);
                s1[nf] += __shfl_down_sync(0xFFFFFFFFu, s1[nf], o);
            }
        __syncthreads();
        float* red = (float*)sm;
        if (lane < 4)
#pragma unroll
            for (int nf = 0; nf < NF; nf++) {
                red[(wid * NF + nf) * 8 + tc * 2 + 0] = s0[nf];
                red[(wid * NF + nf) * 8 + tc * 2 + 1] = s1[nf];
            }
        __syncthreads();
        if (tid < WN * NF * 8) {
            const int wn2 = tid / (NF * 8);
            const int rem = tid - wn2 * NF * 8;
            const int nf = rem >> 3, j = rem & 7;
            float t = 0.f;
#pragma unroll
            for (int w2 = 0; w2 < WM; w2++)
                t += red[((wn2 * WM + w2) * NF + nf) * 8 + j];
            const int n = n0 + wn2 * (COUT / WN) + nf * 8 + j;
            part[((size_t)b * 8 + blockIdx.x) * 128 + n] = t;
        }
    } else {
#pragma unroll
        for (int mf = 0; mf < MF; mf++)
#pragma unroll
            for (int half = 0; half < 2; half++) {
                const int m  = M0 + mf * 16 + g + half * 8;
                const int px = px0 + m;
                const int oy = px >> LOGH, ox = px & (HOUT - 1);
                const size_t base = (((size_t)b * HOUT + oy) * HOUT + ox) * NTOT + n0;
#pragma unroll
                for (int nf = 0; nf < NF; nf++) {
                    const int n = N0 + nf * 8 + tc * 2;
                    const float y0 = fmaxf(acc[mf][nf][half * 2 + 0] + __ldg(bias_g + n), 0.f);
                    const float y1 = fmaxf(acc[mf][nf][half * 2 + 1] + __ldg(bias_g + n + 1), 0.f);
                    const __nv_bfloat16 h0 = __float2bfloat16_rn(y0);
                    const __nv_bfloat16 h1 = __float2bfloat16_rn(y1);
                    const __nv_bfloat16 l0 = __float2bfloat16_rn(y0 - __bfloat162float(h0));
                    const __nv_bfloat16 l1 = __float2bfloat16_rn(y1 - __bfloat162float(h1));
                    *(u32*)(out_h + base + n) =
                        (u32)__bfloat16_as_ushort(h0) | ((u32)__bfloat16_as_ushort(h1) << 16);
                    *(u32*)(out_l + base + n) =
                        (u32)__bfloat16_as_ushort(l0) | ((u32)__bfloat16_as_ushort(l1) << 16);
                }
            }
    }
}

// ---------------------------------------------------------------------------
__global__ void __launch_bounds__(128) fc_k(const float* __restrict__ part,
                                            const float* __restrict__ fw,
                                            const float* __restrict__ fb,
                                            const int* __restrict__ region,
                                            float* __restrict__ out)
{
    __shared__ float f[128];
    const int b = blockIdx.x, tid = threadIdx.x;
    const int r = region[b] & (R_ - 1);
    float s = 0.0f;
#pragma unroll
    for (int q = 0; q < 8; q++) s += part[(b * 8 + q) * 128 + tid];
    f[tid] = s * (1.0f / 1024.0f);
    __syncthreads();
    if (tid < 32) {
        const float* w0 = fw + ((size_t)r * 2 + 0) * 128;
        const float* w1 = fw + ((size_t)r * 2 + 1) * 128;
        float p0 = 0.0f, p1 = 0.0f;
#pragma unroll
        for (int i = tid; i < 128; i += 32) {
            p0 = fmaf(f[i], w0[i], p0);
            p1 = fmaf(f[i], w1[i], p1);
        }
#pragma unroll
        for (int o = 16; o > 0; o >>= 1) {
            p0 += __shfl_down_sync(0xFFFFFFFFu, p0, o);
            p1 += __shfl_down_sync(0xFFFFFFFFu, p1, o);
        }
        if (tid == 0) {
            out[b * 2 + 0] = p0 + fb[r * 2 + 0];
            out[b * 2 + 1] = p1 + fb[r * 2 + 1];
        }
    }
}

// ---------------------------------------------------------------------------
extern "C" void kernel_launch(void* const* d_in, const int* in_sizes, int n_in,
                              void* d_out, int out_size)
{
    const float* image  = (const float*)d_in[0];
    const int*   region = (const int*)d_in[1];
    const float* w1     = (const float*)d_in[2];
    const float* b1     = (const float*)d_in[3];
    const float* w2     = (const float*)d_in[4];
    const float* b2     = (const float*)d_in[5];
    const float* w3     = (const float*)d_in[6];
    const float* b3     = (const float*)d_in[7];
    const float* fw     = (const float*)d_in[8];
    const float* fb     = (const float*)d_in[9];
    float* out = (float*)d_out;

    __nv_bfloat16 *imgh, *imgl, *b1h, *b1l, *b2h, *b2l, *w1img, *w2img, *w3img;
    float *part;
    cudaGetSymbolAddress((void**)&imgh, g_imgh);
    cudaGetSymbolAddress((void**)&imgl, g_imgl);
    cudaGetSymbolAddress((void**)&b1h, g_b1h);
    cudaGetSymbolAddress((void**)&b1l, g_b1l);
    cudaGetSymbolAddress((void**)&b2h, g_b2h);
    cudaGetSymbolAddress((void**)&b2l, g_b2l);
    cudaGetSymbolAddress((void**)&part, g_part);
    cudaGetSymbolAddress((void**)&w1img, g_w1img);
    cudaGetSymbolAddress((void**)&w2img, g_w2img);
    cudaGetSymbolAddress((void**)&w3img, g_w3img);

    prep_all<<<NB_IMG + NB_W1 + NB_W2 + NB_W3, 256>>>(
        image, imgh, imgl, w1, w1img, w2, w2img, w3, w3img);

    const int SM1 = 2 * 18720 + 2 * 32 * 144;     //  46656
    const int SM2 = 2 * (36864 + 2 * 64 * 144);   // 110592 -> 2 CTAs/SM
    const int SM3 = SM2;
    cudaFuncSetAttribute(conv1_k,
                         cudaFuncAttributeMaxDynamicSharedMemorySize, SM1);
    cudaFuncSetAttribute(conv_mma7<32, 5, 64, 64, 64, 6, 4, 2, false>,
                         cudaFuncAttributeMaxDynamicSharedMemorySize, SM2);
    cudaFuncSetAttribute(conv_mma7<64, 6, 64, 128, 32, 5, 4, 2, true>,
                         cudaFuncAttributeMaxDynamicSharedMemorySize, SM3);

    // conv1: direct-from-tile, 4 output rows/block
    conv1_k<<<dim3(32, 1, B_), 256, SM1>>>(
        imgh, imgl, w1img, b1, region, b1h, b1l);
    // conv2: im2col pipeline
    conv_mma7<32, 5, 64, 64, 64, 6, 4, 2, false><<<dim3(32, 1, B_), 256, SM2>>>(
        b1h, b1l, w2img, b2, region, nullptr, b2h, b2l);
    // conv3: N-split + fused GAP
    conv_mma7<64, 6, 64, 128, 32, 5, 4, 2, true><<<dim3(8, 2, B_), 256, SM3>>>(
        b2h, b2l, w3img, b3, region, part, nullptr, nullptr);

    fc_k<<<B_, 128>>>(part, fw, fb, region, out);
}